// round 12
// baseline (speedup 1.0000x reference)
#include <cuda_runtime.h>
#include <math.h>

#define BATCH 16
#define NPTS  1024
#define KNN_K 20
#define BNSC  0.9999950000374997f   // 1/sqrt(1+1e-5)

typedef unsigned long long ull;
typedef unsigned int uint;
typedef unsigned short ushort;

// ---------------- scratch (static device globals; no allocs) ----------------
__device__ float g_xx  [BATCH * NPTS];
__device__ uint  g_key [(size_t)BATCH * NPTS * NPTS];          // 67 MB fenc(dist), exact
__device__ float g_A   [(size_t)BATCH * NPTS * 256];           // [b][n][O]
__device__ float g_Bc  [(size_t)BATCH * NPTS * 256];           // [b][n][O]
__device__ float g_h   [(size_t)BATCH * NPTS * 512];           // [b][n][512]
__device__ unsigned g_pmax[BATCH * 1024];
__device__ float    g_psum[BATCH * 1024];

// ---------------- helpers ----------------
__device__ __forceinline__ ull pk2(float a, float b) {
    ull r; asm("mov.b64 %0, {%1, %2};" : "=l"(r) : "f"(a), "f"(b)); return r;
}
__device__ __forceinline__ void ffma2(ull& d, ull a, ull b) {
    asm("fma.rn.f32x2 %0, %1, %2, %0;" : "+l"(d) : "l"(a), "l"(b));
}
__device__ __forceinline__ unsigned fenc(float v) {
    unsigned u = __float_as_uint(v);
    return u ^ (((int)u >> 31) | 0x80000000u);
}
__device__ __forceinline__ uint redux_max(uint v) {
    uint r; asm("redux.sync.max.u32 %0, %1, 0xffffffff;" : "=r"(r) : "r"(v)); return r;
}
// decode upper-triangle pair index (36 pairs of 8x8 blocks), bi <= bj
__device__ __forceinline__ void tri_decode(int bid, int& bi, int& bj) {
    int rem = bid, r = 0;
    for (;;) { int len = 8 - r; if (rem < len) break; rem -= len; r++; }
    bi = r; bj = r + rem;
}

// ---------------- xx for stage 1 + init pooled accumulators ----------------
__global__ void xx_cn_kernel(const float* __restrict__ x) {
    int n = blockIdx.x * 256 + threadIdx.x;
    int b = blockIdx.y;
    const float* xb = x + (size_t)b * 6 * NPTS;
    float s = 0.f;
    #pragma unroll
    for (int c = 0; c < 6; c++) { float v = xb[c * NPTS + n]; s += v * v; }
    g_xx[b * NPTS + n] = s;
    int i = (blockIdx.y * 4 + blockIdx.x) * 256 + threadIdx.x;  // 0..16383
    g_pmax[i] = 0u;
    g_psum[i] = 0.f;
}

// ---------------- dist stage 1: C=6, [c][n], symmetric (36 blocks) ----------------
__global__ void dist_cn_kernel(const float* __restrict__ x) {
    __shared__ float Xn[6][132], Xm[6][132];
    __shared__ __align__(16) uint sdT[32][132];
    int b = blockIdx.z;
    int bi, bj; tri_decode(blockIdx.x, bi, bj);
    int n0 = bi * 128, m0 = bj * 128;
    int t = threadIdx.x, tx = t & 15, ty = t >> 4;
    ull acc[8][4];
    #pragma unroll
    for (int i = 0; i < 8; i++)
        #pragma unroll
        for (int j = 0; j < 4; j++) acc[i][j] = 0ull;

    for (int idx = t; idx < 6 * 128; idx += 256) {
        int cc = idx >> 7, nn = idx & 127;
        const float* xb = x + (size_t)b * 6 * NPTS + (size_t)cc * NPTS;
        Xn[cc][nn] = xb[n0 + nn];
        Xm[cc][nn] = xb[m0 + nn];
    }
    __syncthreads();
    #pragma unroll
    for (int cc = 0; cc < 6; cc++) {
        float4 A0 = *(const float4*)&Xn[cc][ty * 8];
        float4 A1 = *(const float4*)&Xn[cc][ty * 8 + 4];
        ull a2[8] = { pk2(A0.x,A0.x), pk2(A0.y,A0.y), pk2(A0.z,A0.z), pk2(A0.w,A0.w),
                      pk2(A1.x,A1.x), pk2(A1.y,A1.y), pk2(A1.z,A1.z), pk2(A1.w,A1.w) };
        ull b2[4];
        #pragma unroll
        for (int j = 0; j < 4; j++) b2[j] = *(const ull*)&Xm[cc][2 * tx + 32 * j];
        #pragma unroll
        for (int i = 0; i < 8; i++)
            #pragma unroll
            for (int j = 0; j < 4; j++) ffma2(acc[i][j], a2[i], b2[j]);
    }
    // normal tile write + stash encoded keys back into acc
    #pragma unroll
    for (int i = 0; i < 8; i++) {
        int n = n0 + ty * 8 + i;
        float xn = g_xx[b * NPTS + n];
        uint* krow = g_key + ((size_t)(b * NPTS) + n) * NPTS;
        #pragma unroll
        for (int j = 0; j < 4; j++) {
            int m = m0 + 2 * tx + 32 * j;
            float2 v = *(float2*)&acc[i][j];
            float2 xm = *(const float2*)&g_xx[b * NPTS + m];
            uint2 e;
            e.x = fenc(2.f * v.x - (xn + xm.x));
            e.y = fenc(2.f * v.y - (xn + xm.y));
            *(uint2*)&krow[m] = e;
            acc[i][j] = ((ull)e.y << 32) | (ull)e.x;
        }
    }
    // transposed tile (rows m, cols n) via smem staging
    if (bi != bj) {
        #pragma unroll
        for (int j = 0; j < 4; j++) {
            __syncthreads();
            #pragma unroll
            for (int i = 0; i < 8; i++) {
                ull a = acc[i][j];
                sdT[2 * tx][ty * 8 + i]     = (uint)a;
                sdT[2 * tx + 1][ty * 8 + i] = (uint)(a >> 32);
            }
            __syncthreads();
            #pragma unroll
            for (int s = 0; s < 4; s++) {
                int slot = t + s * 256;
                int row = slot >> 5, c4 = (slot & 31) << 2;
                uint4 v = *(uint4*)&sdT[row][c4];
                *(uint4*)&g_key[((size_t)(b * NPTS) + m0 + 32 * j + row) * NPTS + n0 + c4] = v;
            }
        }
    }
}

// ---------------- dist stages 2-4: [n][c], double-buffered, symmetric ----------------
__global__ void dist_nc_kernel(const float* __restrict__ h, int coff, int C) {
    __shared__ __align__(16) float Xn[2][16][132], Xm[2][16][132];
    int b = blockIdx.z;
    int bi, bj; tri_decode(blockIdx.x, bi, bj);
    int n0 = bi * 128, m0 = bj * 128;
    int t = threadIdx.x, tx = t & 15, ty = t >> 4;
    ull acc[8][4];
    #pragma unroll
    for (int i = 0; i < 8; i++)
        #pragma unroll
        for (int j = 0; j < 4; j++) acc[i][j] = 0ull;

    int nn = t >> 1, cs = (t & 1) * 8;
    const float* pn = h + ((size_t)(b * NPTS) + n0 + nn) * 512 + coff + cs;
    const float* pm = h + ((size_t)(b * NPTS) + m0 + nn) * 512 + coff + cs;
    int K = C >> 4;
    float4 a0, a1, c0r, c1r;

    a0 = *(const float4*)pn;  a1 = *(const float4*)(pn + 4);
    c0r = *(const float4*)pm; c1r = *(const float4*)(pm + 4);
    {
        float* dn = &Xn[0][cs][nn]; float* dm = &Xm[0][cs][nn];
        dn[0*132]=a0.x; dn[1*132]=a0.y; dn[2*132]=a0.z; dn[3*132]=a0.w;
        dn[4*132]=a1.x; dn[5*132]=a1.y; dn[6*132]=a1.z; dn[7*132]=a1.w;
        dm[0*132]=c0r.x; dm[1*132]=c0r.y; dm[2*132]=c0r.z; dm[3*132]=c0r.w;
        dm[4*132]=c1r.x; dm[5*132]=c1r.y; dm[6*132]=c1r.z; dm[7*132]=c1r.w;
    }
    __syncthreads();

    for (int k = 0; k < K; k++) {
        int kn = k + 1;
        if (kn < K) {
            const float* qn = pn + kn * 16;
            const float* qm = pm + kn * 16;
            a0 = *(const float4*)qn;  a1 = *(const float4*)(qn + 4);
            c0r = *(const float4*)qm; c1r = *(const float4*)(qm + 4);
        }
        int p = k & 1;
        #pragma unroll
        for (int cc = 0; cc < 16; cc++) {
            float4 A0 = *(const float4*)&Xn[p][cc][ty * 8];
            float4 A1 = *(const float4*)&Xn[p][cc][ty * 8 + 4];
            ull a2[8] = { pk2(A0.x,A0.x), pk2(A0.y,A0.y), pk2(A0.z,A0.z), pk2(A0.w,A0.w),
                          pk2(A1.x,A1.x), pk2(A1.y,A1.y), pk2(A1.z,A1.z), pk2(A1.w,A1.w) };
            ull b2[4];
            #pragma unroll
            for (int j = 0; j < 4; j++) b2[j] = *(const ull*)&Xm[p][cc][2 * tx + 32 * j];
            #pragma unroll
            for (int i = 0; i < 8; i++)
                #pragma unroll
                for (int j = 0; j < 4; j++) ffma2(acc[i][j], a2[i], b2[j]);
        }
        if (kn < K) {
            int q = kn & 1;
            float* dn = &Xn[q][cs][nn]; float* dm = &Xm[q][cs][nn];
            dn[0*132]=a0.x; dn[1*132]=a0.y; dn[2*132]=a0.z; dn[3*132]=a0.w;
            dn[4*132]=a1.x; dn[5*132]=a1.y; dn[6*132]=a1.z; dn[7*132]=a1.w;
            dm[0*132]=c0r.x; dm[1*132]=c0r.y; dm[2*132]=c0r.z; dm[3*132]=c0r.w;
            dm[4*132]=c1r.x; dm[5*132]=c1r.y; dm[6*132]=c1r.z; dm[7*132]=c1r.w;
        }
        __syncthreads();
    }
    // normal tile write + stash encoded keys back into acc
    #pragma unroll
    for (int i = 0; i < 8; i++) {
        int n = n0 + ty * 8 + i;
        float xn = g_xx[b * NPTS + n];
        uint* krow = g_key + ((size_t)(b * NPTS) + n) * NPTS;
        #pragma unroll
        for (int j = 0; j < 4; j++) {
            int m = m0 + 2 * tx + 32 * j;
            float2 v = *(float2*)&acc[i][j];
            float2 xm = *(const float2*)&g_xx[b * NPTS + m];
            uint2 e;
            e.x = fenc(2.f * v.x - (xn + xm.x));
            e.y = fenc(2.f * v.y - (xn + xm.y));
            *(uint2*)&krow[m] = e;
            acc[i][j] = ((ull)e.y << 32) | (ull)e.x;
        }
    }
    // transposed tile via smem staging (reuse Xn buffers: [2][16][132] == [32][132])
    if (bi != bj) {
        uint (*sdT)[132] = (uint (*)[132])&Xn[0][0][0];
        #pragma unroll
        for (int j = 0; j < 4; j++) {
            __syncthreads();
            #pragma unroll
            for (int i = 0; i < 8; i++) {
                ull a = acc[i][j];
                sdT[2 * tx][ty * 8 + i]     = (uint)a;
                sdT[2 * tx + 1][ty * 8 + i] = (uint)(a >> 32);
            }
            __syncthreads();
            #pragma unroll
            for (int s = 0; s < 4; s++) {
                int slot = t + s * 256;
                int row = slot >> 5, c4 = (slot & 31) << 2;
                uint4 v = *(uint4*)&sdT[row][c4];
                *(uint4*)&g_key[((size_t)(b * NPTS) + m0 + 32 * j + row) * NPTS + n0 + c4] = v;
            }
        }
    }
}

// ---------------- gemmAB: 64(o) x 64(n) tile, writes [n][o] ----------------
__global__ void gemmAB_kernel(const float* __restrict__ x, int cn, int coff, int C, int O,
                              const float* __restrict__ w, const float* __restrict__ g,
                              const float* __restrict__ bias) {
    __shared__ float Wd[16][68], Wl[16][68], Xs[16][68];
    int b = blockIdx.z;
    int o0 = blockIdx.y * 64, n0 = blockIdx.x * 64;
    int t = threadIdx.x, tx = t & 15, ty = t >> 4;
    float aA[4][4] = {}, aB[4][4] = {};
    for (int c0 = 0; c0 < C; c0 += 16) {
        __syncthreads();
        #pragma unroll
        for (int i = 0; i < 4; i++) {
            int idx = t + i * 256;
            int oo = idx >> 4, cc = idx & 15;
            int c = c0 + cc;
            float wd = 0.f, wc = 0.f;
            if (c < C) {
                wd = w[(size_t)(o0 + oo) * 2 * C + c];
                wc = w[(size_t)(o0 + oo) * 2 * C + C + c];
            }
            Wd[cc][oo] = wd; Wl[cc][oo] = wc - wd;
            if (cn) {
                int cc2 = idx >> 6, nn2 = idx & 63;
                int c2 = c0 + cc2;
                float xv = (c2 < C) ? x[(size_t)b * C * NPTS + (size_t)c2 * NPTS + n0 + nn2] : 0.f;
                Xs[cc2][nn2] = xv;
            } else {
                int nn2 = idx >> 4, cc3 = idx & 15;
                int c3 = c0 + cc3;
                float xv = (c3 < C) ? x[((size_t)(b * NPTS) + n0 + nn2) * 512 + coff + c3] : 0.f;
                Xs[cc3][nn2] = xv;
            }
        }
        __syncthreads();
        #pragma unroll
        for (int cc = 0; cc < 16; cc++) {
            float wa[4], wl[4], xv[4];
            #pragma unroll
            for (int i = 0; i < 4; i++) { wa[i] = Wd[cc][tx + 16 * i]; wl[i] = Wl[cc][tx + 16 * i]; }
            #pragma unroll
            for (int j = 0; j < 4; j++) xv[j] = Xs[cc][ty + 16 * j];
            #pragma unroll
            for (int i = 0; i < 4; i++)
                #pragma unroll
                for (int j = 0; j < 4; j++) { aA[i][j] += wa[i] * xv[j]; aB[i][j] += wl[i] * xv[j]; }
        }
    }
    #pragma unroll
    for (int i = 0; i < 4; i++) {
        int o = o0 + tx + 16 * i;
        float s = g[o] * BNSC, bo = bias[o];
        #pragma unroll
        for (int j = 0; j < 4; j++) {
            int n = n0 + ty + 16 * j;
            size_t base = ((size_t)(b * NPTS) + n) * O + o;
            g_A[base]  = s * aA[i][j];
            g_Bc[base] = s * aB[i][j] + bo;
        }
    }
}

// ---------------- fused top-k + gather (+xx): lazy 4-stream merge + REDUX ----------------
// key = ((ull)fenc << 32) | ~index : unique, strict total order (val desc, idx asc).
// 4 groups of 8 per lane, sorted sequentially (low reg pressure), spilled as
// {hi:uint, idx:ushort}. Candidate = max of 4 stream heads. Warp-max via 2x REDUX.
// Keys read with __ldcs (read-once, evict-first) to keep L2 free for A/Bc/h.
#define TKG_WARPS 4
__global__ void topkgather_kernel(int O, int choff) {
    __shared__ uint   sh[TKG_WARPS][32][33];
    __shared__ ushort si[TKG_WARPS][32][33];
    int w = threadIdx.x >> 5, lane = threadIdx.x & 31;
    int rid = blockIdx.x * TKG_WARPS + w;       // = b*NPTS + n
    int b = rid >> 10;
    const uint4* r4 = (const uint4*)(g_key + (size_t)rid * NPTS);

    // sequential per-group: load 8, sort 8 (24 CAS), spill descending
    #pragma unroll
    for (int g = 0; g < 4; g++) {
        ull key[8];
        #pragma unroll
        for (int i = 0; i < 2; i++) {
            uint4 v = __ldcs(&r4[g * 64 + i * 32 + lane]);
            int base = g * 256 + i * 128 + lane * 4;
            key[i*4+0] = ((ull)v.x << 32) | (uint)~(base + 0);
            key[i*4+1] = ((ull)v.y << 32) | (uint)~(base + 1);
            key[i*4+2] = ((ull)v.z << 32) | (uint)~(base + 2);
            key[i*4+3] = ((ull)v.w << 32) | (uint)~(base + 3);
        }
        #pragma unroll
        for (int k2 = 2; k2 <= 8; k2 <<= 1) {
            #pragma unroll
            for (int j = k2 >> 1; j > 0; j >>= 1) {
                #pragma unroll
                for (int i = 0; i < 8; i++) {
                    int l = i ^ j;
                    if (l > i) {
                        ull a = key[i], bb = key[l];
                        bool sw = ((i & k2) == 0) ? (a > bb) : (a < bb);
                        if (sw) { key[i] = bb; key[l] = a; }
                    }
                }
            }
        }
        #pragma unroll
        for (int i = 0; i < 8; i++) {
            ull k = key[7 - i];
            sh[w][g * 8 + i][lane] = (uint)(k >> 32);
            si[w][g * 8 + i][lane] = (ushort)(~(uint)k);
        }
    }

    // lazy 4-stream merge
    #define LDHEAD(row) ( ((ull)sh[w][row][lane] << 32) | (uint)~(uint)si[w][row][lane] )
    ull h0 = LDHEAD(0), h1 = LDHEAD(8), h2 = LDHEAD(16), h3 = LDHEAD(24);
    int c0 = 0, c1 = 0, c2 = 0, c3 = 0;
    ull m01 = h0 > h1 ? h0 : h1, m23 = h2 > h3 ? h2 : h3;
    ull cand = m01 > m23 ? m01 : m23;
    int sel = 0;
    #pragma unroll
    for (int kk = 0; kk < KNN_K; kk++) {
        uint hi = (uint)(cand >> 32), lo = (uint)cand;
        uint mh = redux_max(hi);
        uint ml = redux_max(hi == mh ? lo : 0u);
        if (lane == kk) sel = (int)(~ml);
        if (hi == mh && lo == ml) {     // this lane's candidate consumed
            if      (cand == h0) { c0++; h0 = (c0 < 8) ? LDHEAD(c0)      : 0ull; }
            else if (cand == h1) { c1++; h1 = (c1 < 8) ? LDHEAD(8 + c1)  : 0ull; }
            else if (cand == h2) { c2++; h2 = (c2 < 8) ? LDHEAD(16 + c2) : 0ull; }
            else                 { c3++; h3 = (c3 < 8) ? LDHEAD(24 + c3) : 0ull; }
            m01 = h0 > h1 ? h0 : h1; m23 = h2 > h3 ? h2 : h3;
            cand = m01 > m23 ? m01 : m23;
        }
    }
    #undef LDHEAD

    // gather phase: max over neighbors of A, + B, leaky, write h, fused xx
    size_t rowi = (size_t)rid;
    int O4 = O >> 2;
    const float4* A4 = (const float4*)g_A + (size_t)(b * NPTS) * O4;
    int npass = (O + 127) / 128;
    float ss = 0.f;
    for (int p = 0; p < npass; p++) {
        int o4 = p * 128 + lane * 4;
        bool act = o4 < O;
        float4 m = make_float4(-INFINITY, -INFINITY, -INFINITY, -INFINITY);
        #pragma unroll
        for (int k = 0; k < KNN_K; k++) {
            int j = __shfl_sync(0xffffffffu, sel, k);
            if (act) {
                float4 a = A4[(size_t)j * O4 + (o4 >> 2)];
                m.x = fmaxf(m.x, a.x); m.y = fmaxf(m.y, a.y);
                m.z = fmaxf(m.z, a.z); m.w = fmaxf(m.w, a.w);
            }
        }
        if (act) {
            float4 bb = *(const float4*)&g_Bc[rowi * O + o4];
            float4 r;
            r.x = m.x + bb.x; r.y = m.y + bb.y; r.z = m.z + bb.z; r.w = m.w + bb.w;
            r.x = r.x > 0.f ? r.x : 0.2f * r.x;
            r.y = r.y > 0.f ? r.y : 0.2f * r.y;
            r.z = r.z > 0.f ? r.z : 0.2f * r.z;
            r.w = r.w > 0.f ? r.w : 0.2f * r.w;
            *(float4*)&g_h[rowi * 512 + choff + o4] = r;
            ss += r.x * r.x + r.y * r.y + r.z * r.z + r.w * r.w;
        }
    }
    #pragma unroll
    for (int off = 16; off; off >>= 1) ss += __shfl_down_sync(0xffffffffu, ss, off);
    if (lane == 0) g_xx[rowi] = ss;
}

// ---------------- gemm5 + fused pooling, double-buffered FFMA2 ----------------
__global__ void gemm5_kernel(const float* __restrict__ w5, const float* __restrict__ g5,
                             const float* __restrict__ b5) {
    __shared__ float Ws[2][16][132], Hs[2][16][132];
    int b = blockIdx.z;
    int o0 = blockIdx.y * 128, n0 = blockIdx.x * 128;
    int t = threadIdx.x, tx = t & 15, ty = t >> 4;
    ull acc[8][4];
    #pragma unroll
    for (int i = 0; i < 8; i++)
        #pragma unroll
        for (int j = 0; j < 4; j++) acc[i][j] = 0ull;

    int nn = t >> 1, cs = (t & 1) * 8;
    const float* hrow = g_h + ((size_t)(b * NPTS) + n0 + nn) * 512 + cs;
    const float* wrow = w5 + (size_t)(o0 + nn) * 512 + cs;
    float4 w0, w1, h0, h1;

    w0 = *(const float4*)wrow; w1 = *(const float4*)(wrow + 4);
    h0 = *(const float4*)hrow; h1 = *(const float4*)(hrow + 4);
    {
        float* dw = &Ws[0][cs][nn]; float* dh = &Hs[0][cs][nn];
        dw[0*132]=w0.x; dw[1*132]=w0.y; dw[2*132]=w0.z; dw[3*132]=w0.w;
        dw[4*132]=w1.x; dw[5*132]=w1.y; dw[6*132]=w1.z; dw[7*132]=w1.w;
        dh[0*132]=h0.x; dh[1*132]=h0.y; dh[2*132]=h0.z; dh[3*132]=h0.w;
        dh[4*132]=h1.x; dh[5*132]=h1.y; dh[6*132]=h1.z; dh[7*132]=h1.w;
    }
    __syncthreads();

    for (int k = 0; k < 32; k++) {
        int kn = k + 1;
        if (kn < 32) {
            const float* qw = wrow + kn * 16;
            const float* qh = hrow + kn * 16;
            w0 = *(const float4*)qw; w1 = *(const float4*)(qw + 4);
            h0 = *(const float4*)qh; h1 = *(const float4*)(qh + 4);
        }
        int p = k & 1;
        #pragma unroll
        for (int cc = 0; cc < 16; cc++) {
            float4 A0 = *(const float4*)&Ws[p][cc][ty * 8];
            float4 A1 = *(const float4*)&Ws[p][cc][ty * 8 + 4];
            ull a2[8] = { pk2(A0.x,A0.x), pk2(A0.y,A0.y), pk2(A0.z,A0.z), pk2(A0.w,A0.w),
                          pk2(A1.x,A1.x), pk2(A1.y,A1.y), pk2(A1.z,A1.z), pk2(A1.w,A1.w) };
            ull b2[4];
            #pragma unroll
            for (int j = 0; j < 4; j++) b2[j] = *(const ull*)&Hs[p][cc][2 * tx + 32 * j];
            #pragma unroll
            for (int i = 0; i < 8; i++)
                #pragma unroll
                for (int j = 0; j < 4; j++) ffma2(acc[i][j], a2[i], b2[j]);
        }
        if (kn < 32) {
            int q = kn & 1;
            float* dw = &Ws[q][cs][nn]; float* dh = &Hs[q][cs][nn];
            dw[0*132]=w0.x; dw[1*132]=w0.y; dw[2*132]=w0.z; dw[3*132]=w0.w;
            dw[4*132]=w1.x; dw[5*132]=w1.y; dw[6*132]=w1.z; dw[7*132]=w1.w;
            dh[0*132]=h0.x; dh[1*132]=h0.y; dh[2*132]=h0.z; dh[3*132]=h0.w;
            dh[4*132]=h1.x; dh[5*132]=h1.y; dh[6*132]=h1.z; dh[7*132]=h1.w;
        }
        __syncthreads();
    }
    // epilogue: leaky(bn(.)) then fused max/sum pooling (row o = o0+ty*8+i)
    #pragma unroll
    for (int i = 0; i < 8; i++) {
        int o = o0 + ty * 8 + i;
        float s = g5[o] * BNSC, bo = b5[o];
        float mx = -INFINITY, sm = 0.f;
        #pragma unroll
        for (int j = 0; j < 4; j++) {
            float2 v = *(float2*)&acc[i][j];
            v.x = s * v.x + bo; v.y = s * v.y + bo;
            v.x = v.x > 0.f ? v.x : 0.2f * v.x;
            v.y = v.y > 0.f ? v.y : 0.2f * v.y;
            mx = fmaxf(mx, fmaxf(v.x, v.y));
            sm += v.x + v.y;
        }
        #pragma unroll
        for (int off = 8; off; off >>= 1) {
            mx = fmaxf(mx, __shfl_down_sync(0xffffffffu, mx, off, 16));
            sm += __shfl_down_sync(0xffffffffu, sm, off, 16);
        }
        if (tx == 0) {
            atomicMax(&g_pmax[b * 1024 + o], fenc(mx));
            atomicAdd(&g_psum[b * 1024 + o], sm);
        }
    }
}

// ---------------- MLP head ----------------
__global__ void head_kernel(const float* __restrict__ wl1, const float* __restrict__ g6, const float* __restrict__ b6,
                            const float* __restrict__ wl2, const float* __restrict__ g7, const float* __restrict__ b7,
                            const float* __restrict__ wl21, const float* __restrict__ wl22,
                            const float* __restrict__ g8, const float* __restrict__ b8,
                            const float* __restrict__ wl3, float* __restrict__ out) {
    int b = blockIdx.x, t = threadIdx.x;
    __shared__ float sp[2048], s1[256], s2[128], s3[64], s4[32];
    for (int i = t; i < 1024; i += 256) {
        unsigned e = g_pmax[b * 1024 + i];
        unsigned bits = (e & 0x80000000u) ? (e ^ 0x80000000u) : ~e;
        sp[i] = __uint_as_float(bits);
        sp[1024 + i] = g_psum[b * 1024 + i] * (1.f / 1024.f);
    }
    __syncthreads();
    {
        float acc = 0.f;
        const float* wr = wl1 + (size_t)t * 2048;
        for (int c = 0; c < 2048; c++) acc += sp[c] * wr[c];
        acc = g6[t] * (acc * BNSC) + b6[t];
        s1[t] = acc > 0.f ? acc : 0.2f * acc;
    }
    __syncthreads();
    if (t < 128) {
        float acc = 0.f;
        const float* wr = wl2 + (size_t)t * 256;
        for (int c = 0; c < 256; c++) acc += s1[c] * wr[c];
        acc = g7[t] * (acc * BNSC) + b7[t];
        s2[t] = acc > 0.f ? acc : 0.2f * acc;
    }
    __syncthreads();
    if (t < 64) {
        float acc = 0.f;
        const float* wr = wl21 + (size_t)t * 128;
        for (int c = 0; c < 128; c++) acc += s2[c] * wr[c];
        s3[t] = acc;
    }
    __syncthreads();
    if (t < 32) {
        float acc = 0.f;
        const float* wr = wl22 + (size_t)t * 64;
        for (int c = 0; c < 64; c++) acc += s3[c] * wr[c];
        acc = g8[t] * (acc * BNSC) + b8[t];
        s4[t] = 0.5f * acc * (1.0f + erff(acc * 0.70710678118654752f));
    }
    __syncthreads();
    if (t < 90) {
        float acc = 0.f;
        const float* wr = wl3 + (size_t)t * 32;
        for (int c = 0; c < 32; c++) acc += s4[c] * wr[c];
        out[b * 90 + t] = acc;
    }
}

// ---------------- launcher ----------------
extern "C" void kernel_launch(void* const* d_in, const int* in_sizes, int n_in,
                              void* d_out, int out_size) {
    const float* x   = (const float*)d_in[0];
    const float* w1  = (const float*)d_in[2];
    const float* g1  = (const float*)d_in[3];
    const float* b1  = (const float*)d_in[4];
    const float* w2  = (const float*)d_in[5];
    const float* g2  = (const float*)d_in[6];
    const float* b2  = (const float*)d_in[7];
    const float* w3  = (const float*)d_in[8];
    const float* g3  = (const float*)d_in[9];
    const float* b3  = (const float*)d_in[10];
    const float* w4  = (const float*)d_in[11];
    const float* g4  = (const float*)d_in[12];
    const float* b4  = (const float*)d_in[13];
    const float* w5  = (const float*)d_in[14];
    const float* g5  = (const float*)d_in[15];
    const float* b5  = (const float*)d_in[16];
    const float* wl1 = (const float*)d_in[17];
    const float* g6  = (const float*)d_in[18];
    const float* b6  = (const float*)d_in[19];
    const float* wl2 = (const float*)d_in[20];
    const float* g7  = (const float*)d_in[21];
    const float* b7  = (const float*)d_in[22];
    const float* wl21= (const float*)d_in[23];
    const float* wl22= (const float*)d_in[24];
    const float* g8  = (const float*)d_in[25];
    const float* b8  = (const float*)d_in[26];
    const float* wl3 = (const float*)d_in[27];

    xx_cn_kernel<<<dim3(NPTS / 256, BATCH), 256>>>(x);

    struct St { int cn; int coff; int C; int O; int choff;
                const float* w; const float* g; const float* bb; };
    St st[4] = {
        { 1, 0,   6,   64,  0,   w1, g1, b1 },
        { 0, 0,   64,  64,  64,  w2, g2, b2 },
        { 0, 64,  64,  128, 128, w3, g3, b3 },
        { 0, 128, 128, 256, 256, w4, g4, b4 },
    };

    float* gh = nullptr;
    cudaGetSymbolAddress((void**)&gh, g_h);

    for (int s = 0; s < 4; s++) {
        // gemmAB first, then dist, so the 67 MB key array is L2-hot when
        // topkgather reads it (gemmAB and dist are mutually independent).
        gemmAB_kernel<<<dim3(16, st[s].O / 64, BATCH), 256>>>(
            st[s].cn ? x : gh, st[s].cn, st[s].coff, st[s].C, st[s].O,
            st[s].w, st[s].g, st[s].bb);
        if (st[s].cn)
            dist_cn_kernel<<<dim3(36, 1, BATCH), 256>>>(x);
        else
            dist_nc_kernel<<<dim3(36, 1, BATCH), 256>>>(gh, st[s].coff, st[s].C);
        topkgather_kernel<<<(BATCH * NPTS) / TKG_WARPS, TKG_WARPS * 32>>>(st[s].O, st[s].choff);
    }

    gemm5_kernel<<<dim3(8, 8, BATCH), 256>>>(w5, g5, b5);
    head_kernel <<<BATCH, 256>>>(wl1, g6, b6, wl2, g7, b7, wl21, wl22, g8, b8, wl3,
                                 (float*)d_out);
}

// round 13
// speedup vs baseline: 1.0053x; 1.0053x over previous
#include <cuda_runtime.h>
#include <math.h>

#define BATCH 16
#define NPTS  1024
#define KNN_K 20
#define BNSC  0.9999950000374997f   // 1/sqrt(1+1e-5)

typedef unsigned long long ull;
typedef unsigned int uint;
typedef unsigned short ushort;

// ---------------- scratch (static device globals; no allocs) ----------------
__device__ float g_xx  [BATCH * NPTS];
__device__ uint  g_key [(size_t)BATCH * NPTS * NPTS];          // 67 MB fenc(dist), exact
__device__ float g_A   [(size_t)BATCH * NPTS * 256];           // [b][n][O]
__device__ float g_Bc  [(size_t)BATCH * NPTS * 256];           // [b][n][O]
__device__ float g_h   [(size_t)BATCH * NPTS * 512];           // [b][n][512]
__device__ unsigned g_pmax[BATCH * 1024];
__device__ float    g_psum[BATCH * 1024];

// ---------------- helpers ----------------
__device__ __forceinline__ ull pk2(float a, float b) {
    ull r; asm("mov.b64 %0, {%1, %2};" : "=l"(r) : "f"(a), "f"(b)); return r;
}
__device__ __forceinline__ void ffma2(ull& d, ull a, ull b) {
    asm("fma.rn.f32x2 %0, %1, %2, %0;" : "+l"(d) : "l"(a), "l"(b));
}
__device__ __forceinline__ unsigned fenc(float v) {
    unsigned u = __float_as_uint(v);
    return u ^ (((int)u >> 31) | 0x80000000u);
}
__device__ __forceinline__ uint redux_max(uint v) {
    uint r; asm("redux.sync.max.u32 %0, %1, 0xffffffff;" : "=r"(r) : "r"(v)); return r;
}
// decode upper-triangle pair index (36 pairs of 8x8 blocks), bi <= bj
__device__ __forceinline__ void tri_decode(int bid, int& bi, int& bj) {
    int rem = bid, r = 0;
    for (;;) { int len = 8 - r; if (rem < len) break; rem -= len; r++; }
    bi = r; bj = r + rem;
}

// ---------------- xx for stage 1 + init pooled accumulators ----------------
__global__ void xx_cn_kernel(const float* __restrict__ x) {
    int n = blockIdx.x * 256 + threadIdx.x;
    int b = blockIdx.y;
    const float* xb = x + (size_t)b * 6 * NPTS;
    float s = 0.f;
    #pragma unroll
    for (int c = 0; c < 6; c++) { float v = xb[c * NPTS + n]; s += v * v; }
    g_xx[b * NPTS + n] = s;
    int i = (blockIdx.y * 4 + blockIdx.x) * 256 + threadIdx.x;  // 0..16383
    g_pmax[i] = 0u;
    g_psum[i] = 0.f;
}

// ---------------- dist stage 1: C=6, [c][n], symmetric (36 blocks) ----------------
__global__ void dist_cn_kernel(const float* __restrict__ x) {
    __shared__ float Xn[6][132], Xm[6][132];
    __shared__ __align__(16) uint sdT[32][132];
    int b = blockIdx.z;
    int bi, bj; tri_decode(blockIdx.x, bi, bj);
    int n0 = bi * 128, m0 = bj * 128;
    int t = threadIdx.x, tx = t & 15, ty = t >> 4;
    ull acc[8][4];
    #pragma unroll
    for (int i = 0; i < 8; i++)
        #pragma unroll
        for (int j = 0; j < 4; j++) acc[i][j] = 0ull;

    for (int idx = t; idx < 6 * 128; idx += 256) {
        int cc = idx >> 7, nn = idx & 127;
        const float* xb = x + (size_t)b * 6 * NPTS + (size_t)cc * NPTS;
        Xn[cc][nn] = xb[n0 + nn];
        Xm[cc][nn] = xb[m0 + nn];
    }
    __syncthreads();
    #pragma unroll
    for (int cc = 0; cc < 6; cc++) {
        float4 A0 = *(const float4*)&Xn[cc][ty * 8];
        float4 A1 = *(const float4*)&Xn[cc][ty * 8 + 4];
        ull a2[8] = { pk2(A0.x,A0.x), pk2(A0.y,A0.y), pk2(A0.z,A0.z), pk2(A0.w,A0.w),
                      pk2(A1.x,A1.x), pk2(A1.y,A1.y), pk2(A1.z,A1.z), pk2(A1.w,A1.w) };
        ull b2[4];
        #pragma unroll
        for (int j = 0; j < 4; j++) b2[j] = *(const ull*)&Xm[cc][2 * tx + 32 * j];
        #pragma unroll
        for (int i = 0; i < 8; i++)
            #pragma unroll
            for (int j = 0; j < 4; j++) ffma2(acc[i][j], a2[i], b2[j]);
    }
    // normal tile write + stash encoded keys back into acc
    #pragma unroll
    for (int i = 0; i < 8; i++) {
        int n = n0 + ty * 8 + i;
        float xn = g_xx[b * NPTS + n];
        uint* krow = g_key + ((size_t)(b * NPTS) + n) * NPTS;
        #pragma unroll
        for (int j = 0; j < 4; j++) {
            int m = m0 + 2 * tx + 32 * j;
            float2 v = *(float2*)&acc[i][j];
            float2 xm = *(const float2*)&g_xx[b * NPTS + m];
            uint2 e;
            e.x = fenc(2.f * v.x - (xn + xm.x));
            e.y = fenc(2.f * v.y - (xn + xm.y));
            *(uint2*)&krow[m] = e;
            acc[i][j] = ((ull)e.y << 32) | (ull)e.x;
        }
    }
    // transposed tile (rows m, cols n) via smem staging
    if (bi != bj) {
        #pragma unroll
        for (int j = 0; j < 4; j++) {
            __syncthreads();
            #pragma unroll
            for (int i = 0; i < 8; i++) {
                ull a = acc[i][j];
                sdT[2 * tx][ty * 8 + i]     = (uint)a;
                sdT[2 * tx + 1][ty * 8 + i] = (uint)(a >> 32);
            }
            __syncthreads();
            #pragma unroll
            for (int s = 0; s < 4; s++) {
                int slot = t + s * 256;
                int row = slot >> 5, c4 = (slot & 31) << 2;
                uint4 v = *(uint4*)&sdT[row][c4];
                *(uint4*)&g_key[((size_t)(b * NPTS) + m0 + 32 * j + row) * NPTS + n0 + c4] = v;
            }
        }
    }
}

// ---------------- dist stages 2-4: [n][c], double-buffered, symmetric ----------------
__global__ void dist_nc_kernel(const float* __restrict__ h, int coff, int C) {
    __shared__ __align__(16) float Xn[2][16][132], Xm[2][16][132];
    int b = blockIdx.z;
    int bi, bj; tri_decode(blockIdx.x, bi, bj);
    int n0 = bi * 128, m0 = bj * 128;
    int t = threadIdx.x, tx = t & 15, ty = t >> 4;
    ull acc[8][4];
    #pragma unroll
    for (int i = 0; i < 8; i++)
        #pragma unroll
        for (int j = 0; j < 4; j++) acc[i][j] = 0ull;

    int nn = t >> 1, cs = (t & 1) * 8;
    const float* pn = h + ((size_t)(b * NPTS) + n0 + nn) * 512 + coff + cs;
    const float* pm = h + ((size_t)(b * NPTS) + m0 + nn) * 512 + coff + cs;
    int K = C >> 4;
    float4 a0, a1, c0r, c1r;

    a0 = *(const float4*)pn;  a1 = *(const float4*)(pn + 4);
    c0r = *(const float4*)pm; c1r = *(const float4*)(pm + 4);
    {
        float* dn = &Xn[0][cs][nn]; float* dm = &Xm[0][cs][nn];
        dn[0*132]=a0.x; dn[1*132]=a0.y; dn[2*132]=a0.z; dn[3*132]=a0.w;
        dn[4*132]=a1.x; dn[5*132]=a1.y; dn[6*132]=a1.z; dn[7*132]=a1.w;
        dm[0*132]=c0r.x; dm[1*132]=c0r.y; dm[2*132]=c0r.z; dm[3*132]=c0r.w;
        dm[4*132]=c1r.x; dm[5*132]=c1r.y; dm[6*132]=c1r.z; dm[7*132]=c1r.w;
    }
    __syncthreads();

    for (int k = 0; k < K; k++) {
        int kn = k + 1;
        if (kn < K) {
            const float* qn = pn + kn * 16;
            const float* qm = pm + kn * 16;
            a0 = *(const float4*)qn;  a1 = *(const float4*)(qn + 4);
            c0r = *(const float4*)qm; c1r = *(const float4*)(qm + 4);
        }
        int p = k & 1;
        #pragma unroll
        for (int cc = 0; cc < 16; cc++) {
            float4 A0 = *(const float4*)&Xn[p][cc][ty * 8];
            float4 A1 = *(const float4*)&Xn[p][cc][ty * 8 + 4];
            ull a2[8] = { pk2(A0.x,A0.x), pk2(A0.y,A0.y), pk2(A0.z,A0.z), pk2(A0.w,A0.w),
                          pk2(A1.x,A1.x), pk2(A1.y,A1.y), pk2(A1.z,A1.z), pk2(A1.w,A1.w) };
            ull b2[4];
            #pragma unroll
            for (int j = 0; j < 4; j++) b2[j] = *(const ull*)&Xm[p][cc][2 * tx + 32 * j];
            #pragma unroll
            for (int i = 0; i < 8; i++)
                #pragma unroll
                for (int j = 0; j < 4; j++) ffma2(acc[i][j], a2[i], b2[j]);
        }
        if (kn < K) {
            int q = kn & 1;
            float* dn = &Xn[q][cs][nn]; float* dm = &Xm[q][cs][nn];
            dn[0*132]=a0.x; dn[1*132]=a0.y; dn[2*132]=a0.z; dn[3*132]=a0.w;
            dn[4*132]=a1.x; dn[5*132]=a1.y; dn[6*132]=a1.z; dn[7*132]=a1.w;
            dm[0*132]=c0r.x; dm[1*132]=c0r.y; dm[2*132]=c0r.z; dm[3*132]=c0r.w;
            dm[4*132]=c1r.x; dm[5*132]=c1r.y; dm[6*132]=c1r.z; dm[7*132]=c1r.w;
        }
        __syncthreads();
    }
    // normal tile write + stash encoded keys back into acc
    #pragma unroll
    for (int i = 0; i < 8; i++) {
        int n = n0 + ty * 8 + i;
        float xn = g_xx[b * NPTS + n];
        uint* krow = g_key + ((size_t)(b * NPTS) + n) * NPTS;
        #pragma unroll
        for (int j = 0; j < 4; j++) {
            int m = m0 + 2 * tx + 32 * j;
            float2 v = *(float2*)&acc[i][j];
            float2 xm = *(const float2*)&g_xx[b * NPTS + m];
            uint2 e;
            e.x = fenc(2.f * v.x - (xn + xm.x));
            e.y = fenc(2.f * v.y - (xn + xm.y));
            *(uint2*)&krow[m] = e;
            acc[i][j] = ((ull)e.y << 32) | (ull)e.x;
        }
    }
    // transposed tile via smem staging (reuse Xn buffers: [2][16][132] == [32][132])
    if (bi != bj) {
        uint (*sdT)[132] = (uint (*)[132])&Xn[0][0][0];
        #pragma unroll
        for (int j = 0; j < 4; j++) {
            __syncthreads();
            #pragma unroll
            for (int i = 0; i < 8; i++) {
                ull a = acc[i][j];
                sdT[2 * tx][ty * 8 + i]     = (uint)a;
                sdT[2 * tx + 1][ty * 8 + i] = (uint)(a >> 32);
            }
            __syncthreads();
            #pragma unroll
            for (int s = 0; s < 4; s++) {
                int slot = t + s * 256;
                int row = slot >> 5, c4 = (slot & 31) << 2;
                uint4 v = *(uint4*)&sdT[row][c4];
                *(uint4*)&g_key[((size_t)(b * NPTS) + m0 + 32 * j + row) * NPTS + n0 + c4] = v;
            }
        }
    }
}

// ---------------- gemmAB: 64(o) x 64(n) tile, writes [n][o] ----------------
__global__ void gemmAB_kernel(const float* __restrict__ x, int cn, int coff, int C, int O,
                              const float* __restrict__ w, const float* __restrict__ g,
                              const float* __restrict__ bias) {
    __shared__ float Wd[16][68], Wl[16][68], Xs[16][68];
    int b = blockIdx.z;
    int o0 = blockIdx.y * 64, n0 = blockIdx.x * 64;
    int t = threadIdx.x, tx = t & 15, ty = t >> 4;
    float aA[4][4] = {}, aB[4][4] = {};
    for (int c0 = 0; c0 < C; c0 += 16) {
        __syncthreads();
        #pragma unroll
        for (int i = 0; i < 4; i++) {
            int idx = t + i * 256;
            int oo = idx >> 4, cc = idx & 15;
            int c = c0 + cc;
            float wd = 0.f, wc = 0.f;
            if (c < C) {
                wd = w[(size_t)(o0 + oo) * 2 * C + c];
                wc = w[(size_t)(o0 + oo) * 2 * C + C + c];
            }
            Wd[cc][oo] = wd; Wl[cc][oo] = wc - wd;
            if (cn) {
                int cc2 = idx >> 6, nn2 = idx & 63;
                int c2 = c0 + cc2;
                float xv = (c2 < C) ? x[(size_t)b * C * NPTS + (size_t)c2 * NPTS + n0 + nn2] : 0.f;
                Xs[cc2][nn2] = xv;
            } else {
                int nn2 = idx >> 4, cc3 = idx & 15;
                int c3 = c0 + cc3;
                float xv = (c3 < C) ? x[((size_t)(b * NPTS) + n0 + nn2) * 512 + coff + c3] : 0.f;
                Xs[cc3][nn2] = xv;
            }
        }
        __syncthreads();
        #pragma unroll
        for (int cc = 0; cc < 16; cc++) {
            float wa[4], wl[4], xv[4];
            #pragma unroll
            for (int i = 0; i < 4; i++) { wa[i] = Wd[cc][tx + 16 * i]; wl[i] = Wl[cc][tx + 16 * i]; }
            #pragma unroll
            for (int j = 0; j < 4; j++) xv[j] = Xs[cc][ty + 16 * j];
            #pragma unroll
            for (int i = 0; i < 4; i++)
                #pragma unroll
                for (int j = 0; j < 4; j++) { aA[i][j] += wa[i] * xv[j]; aB[i][j] += wl[i] * xv[j]; }
        }
    }
    #pragma unroll
    for (int i = 0; i < 4; i++) {
        int o = o0 + tx + 16 * i;
        float s = g[o] * BNSC, bo = bias[o];
        #pragma unroll
        for (int j = 0; j < 4; j++) {
            int n = n0 + ty + 16 * j;
            size_t base = ((size_t)(b * NPTS) + n) * O + o;
            g_A[base]  = s * aA[i][j];
            g_Bc[base] = s * aB[i][j] + bo;
        }
    }
}

// ---------------- fused top-k + gather (+xx): lazy 4-stream merge + REDUX ----------------
// key = ((ull)fenc << 32) | ~index : unique, strict total order (val desc, idx asc).
// 4 groups of 8 per lane, sorted sequentially (low reg pressure), spilled as
// {hi:uint, idx:ushort}. Candidate = max of 4 stream heads. Warp-max via 2x REDUX.
#define TKG_WARPS 4
__global__ void topkgather_kernel(int O, int choff) {
    __shared__ uint   sh[TKG_WARPS][32][33];
    __shared__ ushort si[TKG_WARPS][32][33];
    int w = threadIdx.x >> 5, lane = threadIdx.x & 31;
    int rid = blockIdx.x * TKG_WARPS + w;       // = b*NPTS + n
    int b = rid >> 10;
    const uint4* r4 = (const uint4*)(g_key + (size_t)rid * NPTS);

    // sequential per-group: load 8, sort 8 (24 CAS), spill descending
    #pragma unroll
    for (int g = 0; g < 4; g++) {
        ull key[8];
        #pragma unroll
        for (int i = 0; i < 2; i++) {
            uint4 v = __ldcs(&r4[g * 64 + i * 32 + lane]);
            int base = g * 256 + i * 128 + lane * 4;
            key[i*4+0] = ((ull)v.x << 32) | (uint)~(base + 0);
            key[i*4+1] = ((ull)v.y << 32) | (uint)~(base + 1);
            key[i*4+2] = ((ull)v.z << 32) | (uint)~(base + 2);
            key[i*4+3] = ((ull)v.w << 32) | (uint)~(base + 3);
        }
        #pragma unroll
        for (int k2 = 2; k2 <= 8; k2 <<= 1) {
            #pragma unroll
            for (int j = k2 >> 1; j > 0; j >>= 1) {
                #pragma unroll
                for (int i = 0; i < 8; i++) {
                    int l = i ^ j;
                    if (l > i) {
                        ull a = key[i], bb = key[l];
                        bool sw = ((i & k2) == 0) ? (a > bb) : (a < bb);
                        if (sw) { key[i] = bb; key[l] = a; }
                    }
                }
            }
        }
        #pragma unroll
        for (int i = 0; i < 8; i++) {
            ull k = key[7 - i];
            sh[w][g * 8 + i][lane] = (uint)(k >> 32);
            si[w][g * 8 + i][lane] = (ushort)(~(uint)k);
        }
    }

    // lazy 4-stream merge
    #define LDHEAD(row) ( ((ull)sh[w][row][lane] << 32) | (uint)~(uint)si[w][row][lane] )
    ull h0 = LDHEAD(0), h1 = LDHEAD(8), h2 = LDHEAD(16), h3 = LDHEAD(24);
    int c0 = 0, c1 = 0, c2 = 0, c3 = 0;
    ull m01 = h0 > h1 ? h0 : h1, m23 = h2 > h3 ? h2 : h3;
    ull cand = m01 > m23 ? m01 : m23;
    int sel = 0;
    #pragma unroll
    for (int kk = 0; kk < KNN_K; kk++) {
        uint hi = (uint)(cand >> 32), lo = (uint)cand;
        uint mh = redux_max(hi);
        uint ml = redux_max(hi == mh ? lo : 0u);
        if (lane == kk) sel = (int)(~ml);
        if (hi == mh && lo == ml) {     // this lane's candidate consumed
            if      (cand == h0) { c0++; h0 = (c0 < 8) ? LDHEAD(c0)      : 0ull; }
            else if (cand == h1) { c1++; h1 = (c1 < 8) ? LDHEAD(8 + c1)  : 0ull; }
            else if (cand == h2) { c2++; h2 = (c2 < 8) ? LDHEAD(16 + c2) : 0ull; }
            else                 { c3++; h3 = (c3 < 8) ? LDHEAD(24 + c3) : 0ull; }
            m01 = h0 > h1 ? h0 : h1; m23 = h2 > h3 ? h2 : h3;
            cand = m01 > m23 ? m01 : m23;
        }
    }
    #undef LDHEAD

    // gather phase: max over neighbors of A, + B, leaky, write h, fused xx
    size_t rowi = (size_t)rid;
    int O4 = O >> 2;
    const float4* A4 = (const float4*)g_A + (size_t)(b * NPTS) * O4;
    int npass = (O + 127) / 128;
    float ss = 0.f;
    for (int p = 0; p < npass; p++) {
        int o4 = p * 128 + lane * 4;
        bool act = o4 < O;
        float4 m = make_float4(-INFINITY, -INFINITY, -INFINITY, -INFINITY);
        #pragma unroll
        for (int k = 0; k < KNN_K; k++) {
            int j = __shfl_sync(0xffffffffu, sel, k);
            if (act) {
                float4 a = A4[(size_t)j * O4 + (o4 >> 2)];
                m.x = fmaxf(m.x, a.x); m.y = fmaxf(m.y, a.y);
                m.z = fmaxf(m.z, a.z); m.w = fmaxf(m.w, a.w);
            }
        }
        if (act) {
            float4 bb = *(const float4*)&g_Bc[rowi * O + o4];
            float4 r;
            r.x = m.x + bb.x; r.y = m.y + bb.y; r.z = m.z + bb.z; r.w = m.w + bb.w;
            r.x = r.x > 0.f ? r.x : 0.2f * r.x;
            r.y = r.y > 0.f ? r.y : 0.2f * r.y;
            r.z = r.z > 0.f ? r.z : 0.2f * r.z;
            r.w = r.w > 0.f ? r.w : 0.2f * r.w;
            *(float4*)&g_h[rowi * 512 + choff + o4] = r;
            ss += r.x * r.x + r.y * r.y + r.z * r.z + r.w * r.w;
        }
    }
    #pragma unroll
    for (int off = 16; off; off >>= 1) ss += __shfl_down_sync(0xffffffffu, ss, off);
    if (lane == 0) g_xx[rowi] = ss;
}

// ---------------- gemm5 + fused pooling, double-buffered FFMA2 ----------------
__global__ void gemm5_kernel(const float* __restrict__ w5, const float* __restrict__ g5,
                             const float* __restrict__ b5) {
    __shared__ float Ws[2][16][132], Hs[2][16][132];
    int b = blockIdx.z;
    int o0 = blockIdx.y * 128, n0 = blockIdx.x * 128;
    int t = threadIdx.x, tx = t & 15, ty = t >> 4;
    ull acc[8][4];
    #pragma unroll
    for (int i = 0; i < 8; i++)
        #pragma unroll
        for (int j = 0; j < 4; j++) acc[i][j] = 0ull;

    int nn = t >> 1, cs = (t & 1) * 8;
    const float* hrow = g_h + ((size_t)(b * NPTS) + n0 + nn) * 512 + cs;
    const float* wrow = w5 + (size_t)(o0 + nn) * 512 + cs;
    float4 w0, w1, h0, h1;

    w0 = *(const float4*)wrow; w1 = *(const float4*)(wrow + 4);
    h0 = *(const float4*)hrow; h1 = *(const float4*)(hrow + 4);
    {
        float* dw = &Ws[0][cs][nn]; float* dh = &Hs[0][cs][nn];
        dw[0*132]=w0.x; dw[1*132]=w0.y; dw[2*132]=w0.z; dw[3*132]=w0.w;
        dw[4*132]=w1.x; dw[5*132]=w1.y; dw[6*132]=w1.z; dw[7*132]=w1.w;
        dh[0*132]=h0.x; dh[1*132]=h0.y; dh[2*132]=h0.z; dh[3*132]=h0.w;
        dh[4*132]=h1.x; dh[5*132]=h1.y; dh[6*132]=h1.z; dh[7*132]=h1.w;
    }
    __syncthreads();

    for (int k = 0; k < 32; k++) {
        int kn = k + 1;
        if (kn < 32) {
            const float* qw = wrow + kn * 16;
            const float* qh = hrow + kn * 16;
            w0 = *(const float4*)qw; w1 = *(const float4*)(qw + 4);
            h0 = *(const float4*)qh; h1 = *(const float4*)(qh + 4);
        }
        int p = k & 1;
        #pragma unroll
        for (int cc = 0; cc < 16; cc++) {
            float4 A0 = *(const float4*)&Ws[p][cc][ty * 8];
            float4 A1 = *(const float4*)&Ws[p][cc][ty * 8 + 4];
            ull a2[8] = { pk2(A0.x,A0.x), pk2(A0.y,A0.y), pk2(A0.z,A0.z), pk2(A0.w,A0.w),
                          pk2(A1.x,A1.x), pk2(A1.y,A1.y), pk2(A1.z,A1.z), pk2(A1.w,A1.w) };
            ull b2[4];
            #pragma unroll
            for (int j = 0; j < 4; j++) b2[j] = *(const ull*)&Hs[p][cc][2 * tx + 32 * j];
            #pragma unroll
            for (int i = 0; i < 8; i++)
                #pragma unroll
                for (int j = 0; j < 4; j++) ffma2(acc[i][j], a2[i], b2[j]);
        }
        if (kn < 32) {
            int q = kn & 1;
            float* dw = &Ws[q][cs][nn]; float* dh = &Hs[q][cs][nn];
            dw[0*132]=w0.x; dw[1*132]=w0.y; dw[2*132]=w0.z; dw[3*132]=w0.w;
            dw[4*132]=w1.x; dw[5*132]=w1.y; dw[6*132]=w1.z; dw[7*132]=w1.w;
            dh[0*132]=h0.x; dh[1*132]=h0.y; dh[2*132]=h0.z; dh[3*132]=h0.w;
            dh[4*132]=h1.x; dh[5*132]=h1.y; dh[6*132]=h1.z; dh[7*132]=h1.w;
        }
        __syncthreads();
    }
    // epilogue: leaky(bn(.)) then fused max/sum pooling (row o = o0+ty*8+i)
    #pragma unroll
    for (int i = 0; i < 8; i++) {
        int o = o0 + ty * 8 + i;
        float s = g5[o] * BNSC, bo = b5[o];
        float mx = -INFINITY, sm = 0.f;
        #pragma unroll
        for (int j = 0; j < 4; j++) {
            float2 v = *(float2*)&acc[i][j];
            v.x = s * v.x + bo; v.y = s * v.y + bo;
            v.x = v.x > 0.f ? v.x : 0.2f * v.x;
            v.y = v.y > 0.f ? v.y : 0.2f * v.y;
            mx = fmaxf(mx, fmaxf(v.x, v.y));
            sm += v.x + v.y;
        }
        #pragma unroll
        for (int off = 8; off; off >>= 1) {
            mx = fmaxf(mx, __shfl_down_sync(0xffffffffu, mx, off, 16));
            sm += __shfl_down_sync(0xffffffffu, sm, off, 16);
        }
        if (tx == 0) {
            atomicMax(&g_pmax[b * 1024 + o], fenc(mx));
            atomicAdd(&g_psum[b * 1024 + o], sm);
        }
    }
}

// ---------------- MLP head ----------------
__global__ void head_kernel(const float* __restrict__ wl1, const float* __restrict__ g6, const float* __restrict__ b6,
                            const float* __restrict__ wl2, const float* __restrict__ g7, const float* __restrict__ b7,
                            const float* __restrict__ wl21, const float* __restrict__ wl22,
                            const float* __restrict__ g8, const float* __restrict__ b8,
                            const float* __restrict__ wl3, float* __restrict__ out) {
    int b = blockIdx.x, t = threadIdx.x;
    __shared__ float sp[2048], s1[256], s2[128], s3[64], s4[32];
    for (int i = t; i < 1024; i += 256) {
        unsigned e = g_pmax[b * 1024 + i];
        unsigned bits = (e & 0x80000000u) ? (e ^ 0x80000000u) : ~e;
        sp[i] = __uint_as_float(bits);
        sp[1024 + i] = g_psum[b * 1024 + i] * (1.f / 1024.f);
    }
    __syncthreads();
    {
        float acc = 0.f;
        const float* wr = wl1 + (size_t)t * 2048;
        for (int c = 0; c < 2048; c++) acc += sp[c] * wr[c];
        acc = g6[t] * (acc * BNSC) + b6[t];
        s1[t] = acc > 0.f ? acc : 0.2f * acc;
    }
    __syncthreads();
    if (t < 128) {
        float acc = 0.f;
        const float* wr = wl2 + (size_t)t * 256;
        for (int c = 0; c < 256; c++) acc += s1[c] * wr[c];
        acc = g7[t] * (acc * BNSC) + b7[t];
        s2[t] = acc > 0.f ? acc : 0.2f * acc;
    }
    __syncthreads();
    if (t < 64) {
        float acc = 0.f;
        const float* wr = wl21 + (size_t)t * 128;
        for (int c = 0; c < 128; c++) acc += s2[c] * wr[c];
        s3[t] = acc;
    }
    __syncthreads();
    if (t < 32) {
        float acc = 0.f;
        const float* wr = wl22 + (size_t)t * 64;
        for (int c = 0; c < 64; c++) acc += s3[c] * wr[c];
        acc = g8[t] * (acc * BNSC) + b8[t];
        s4[t] = 0.5f * acc * (1.0f + erff(acc * 0.70710678118654752f));
    }
    __syncthreads();
    if (t < 90) {
        float acc = 0.f;
        const float* wr = wl3 + (size_t)t * 32;
        for (int c = 0; c < 32; c++) acc += s4[c] * wr[c];
        out[b * 90 + t] = acc;
    }
}

// ---------------- launcher: fork/join so gemmAB overlaps dist ----------------
extern "C" void kernel_launch(void* const* d_in, const int* in_sizes, int n_in,
                              void* d_out, int out_size) {
    const float* x   = (const float*)d_in[0];
    const float* w1  = (const float*)d_in[2];
    const float* g1  = (const float*)d_in[3];
    const float* b1  = (const float*)d_in[4];
    const float* w2  = (const float*)d_in[5];
    const float* g2  = (const float*)d_in[6];
    const float* b2  = (const float*)d_in[7];
    const float* w3  = (const float*)d_in[8];
    const float* g3  = (const float*)d_in[9];
    const float* b3  = (const float*)d_in[10];
    const float* w4  = (const float*)d_in[11];
    const float* g4  = (const float*)d_in[12];
    const float* b4  = (const float*)d_in[13];
    const float* w5  = (const float*)d_in[14];
    const float* g5  = (const float*)d_in[15];
    const float* b5  = (const float*)d_in[16];
    const float* wl1 = (const float*)d_in[17];
    const float* g6  = (const float*)d_in[18];
    const float* b6  = (const float*)d_in[19];
    const float* wl2 = (const float*)d_in[20];
    const float* g7  = (const float*)d_in[21];
    const float* b7  = (const float*)d_in[22];
    const float* wl21= (const float*)d_in[23];
    const float* wl22= (const float*)d_in[24];
    const float* g8  = (const float*)d_in[25];
    const float* b8  = (const float*)d_in[26];
    const float* wl3 = (const float*)d_in[27];

    // Lazily created on the FIRST (uncaptured, correctness) call; reused on
    // the capture call. Host-side objects only — no device allocation.
    static cudaStream_t s2 = nullptr;
    static cudaEvent_t evF = nullptr, evJ = nullptr;
    if (s2 == nullptr) {
        cudaStreamCreateWithFlags(&s2, cudaStreamNonBlocking);
        cudaEventCreateWithFlags(&evF, cudaEventDisableTiming);
        cudaEventCreateWithFlags(&evJ, cudaEventDisableTiming);
    }

    xx_cn_kernel<<<dim3(NPTS / 256, BATCH), 256>>>(x);

    struct St { int cn; int coff; int C; int O; int choff;
                const float* w; const float* g; const float* bb; };
    St st[4] = {
        { 1, 0,   6,   64,  0,   w1, g1, b1 },
        { 0, 0,   64,  64,  64,  w2, g2, b2 },
        { 0, 64,  64,  128, 128, w3, g3, b3 },
        { 0, 128, 128, 256, 256, w4, g4, b4 },
    };

    float* gh = nullptr;
    cudaGetSymbolAddress((void**)&gh, g_h);

    for (int s = 0; s < 4; s++) {
        // fork: gemmAB(s) runs on side stream, concurrent with dist(s).
        // Both depend only on h from stage s-1 (origin-stream order covers it).
        cudaEventRecord(evF, 0);
        cudaStreamWaitEvent(s2, evF, 0);
        gemmAB_kernel<<<dim3(16, st[s].O / 64, BATCH), 256, 0, s2>>>(
            st[s].cn ? x : gh, st[s].cn, st[s].coff, st[s].C, st[s].O,
            st[s].w, st[s].g, st[s].bb);
        cudaEventRecord(evJ, s2);

        if (st[s].cn)
            dist_cn_kernel<<<dim3(36, 1, BATCH), 256>>>(x);
        else
            dist_nc_kernel<<<dim3(36, 1, BATCH), 256>>>(gh, st[s].coff, st[s].C);

        // join: topkgather needs both dist (keys) and gemmAB (A/Bc).
        cudaStreamWaitEvent(0, evJ, 0);
        topkgather_kernel<<<(BATCH * NPTS) / TKG_WARPS, TKG_WARPS * 32>>>(st[s].O, st[s].choff);
    }

    gemm5_kernel<<<dim3(8, 8, BATCH), 256>>>(w5, g5, b5);
    head_kernel <<<BATCH, 256>>>(wl1, g6, b6, wl2, g7, b7, wl21, wl22, g8, b8, wl3,
                                 (float*)d_out);
}